// round 7
// baseline (speedup 1.0000x reference)
#include <cuda_runtime.h>

#define BB 64
#define TT 4096
#define DD 128
#define HH 128
#define GG 384            // 3*H, gates [r, z, n]

#define NCTA  148
#define N_G1  20          // gemm1 CTAs
// roles after prologue: [0,64) rec0, [64,128) rec1, [128,148) gemm1

typedef unsigned long long u64;

// Scratch (device globals — no allocation allowed).
__device__ float g_gi0[(size_t)TT * BB * GG];
__device__ float g_gi1[(size_t)TT * BB * GG];
__device__ float g_h0 [(size_t)TT * BB * HH];
__device__ unsigned g_f_gi0[TT];   // gi0[t] ready (target 1)
__device__ unsigned g_f_h0 [TT];   // h0[t] ready  (target 64)
__device__ unsigned g_f_gi1[TT];   // gi1[t] ready (target 1)

// ---- packed f32x2 + activation helpers -----------------------------------
__device__ __forceinline__ void fma2(u64& d, u64 a, u64 b) {
    asm("fma.rn.f32x2 %0, %1, %2, %0;" : "+l"(d) : "l"(a), "l"(b));
}
__device__ __forceinline__ u64 f2u(float x, float y) {
    u64 v; asm("mov.b64 %0, {%1,%2};" : "=l"(v) : "f"(x), "f"(y)); return v;
}
__device__ __forceinline__ float hsum(u64 a, u64 b) {
    float xl, xh, yl, yh;
    asm("mov.b64 {%0,%1}, %2;" : "=f"(xl), "=f"(xh) : "l"(a));
    asm("mov.b64 {%0,%1}, %2;" : "=f"(yl), "=f"(yh) : "l"(b));
    return (xl + xh) + (yl + yh);
}
__device__ __forceinline__ float fsig(float x) {
    return __fdividef(1.0f, 1.0f + __expf(-x));
}
__device__ __forceinline__ float ftanh(float x) {
    return 1.0f - __fdividef(2.0f, __expf(2.0f * x) + 1.0f);
}

// ---- flag primitives (gpu-scope release/acquire) -------------------------
__device__ __forceinline__ unsigned ld_acq(const unsigned* p) {
    unsigned v;
    asm volatile("ld.acquire.gpu.global.b32 %0, [%1];" : "=r"(v) : "l"(p));
    return v;
}
__device__ __forceinline__ void red_rel(unsigned* p) {
    asm volatile("red.release.gpu.global.add.u32 [%0], 1;" :: "l"(p) : "memory");
}
__device__ __forceinline__ void spin_ge(const unsigned* p, unsigned target) {
    while (ld_acq(p) < target) { __nanosleep(64); }
}

__global__ void zero_flags() {
    int i = blockIdx.x * blockDim.x + threadIdx.x;
    if (i < TT) { g_f_gi0[i] = 0; g_f_h0[i] = 0; g_f_gi1[i] = 0; }
}

// ---------------------------------------------------------------------------
struct SmemRec {
    float h[128];
    float gh[384];
};
struct SmemGemm {
    float x[4][128];
};
union SmemAll { SmemRec r; SmemGemm g; };

// ---------------------------------------------------------------------------
// GEMM role: gi[t] = act @ W^T + bias for t = t0, t0+stride, ...
//   which=0: act rows = x[b][t][:]  (no dependency)     -> g_gi0, flag fin0
//   which=1: act rows = h0[t][b][:] (wait g_f_h0[t]=64) -> g_gi1, flag fin1
// ---------------------------------------------------------------------------
__device__ void gemm_role(SmemAll* sm,
                          const float* __restrict__ X,
                          const float* __restrict__ W,
                          const float* __restrict__ bias,
                          int which, int t0, int stride)
{
    const int j = threadIdx.x;

    u64 w[64];
    {
        const ulonglong2* wr = (const ulonglong2*)(W + (size_t)j * 128);
        #pragma unroll
        for (int k = 0; k < 32; k++) { ulonglong2 v = wr[k]; w[2*k] = v.x; w[2*k+1] = v.y; }
    }
    const float bj = bias[j];
    float* dst = which ? g_gi1 : g_gi0;
    unsigned* fout = which ? g_f_gi1 : g_f_gi0;

    for (int t = t0; t < TT; t += stride) {
        if (which == 1 && j == 0) spin_ge(&g_f_h0[t], 64);
        __syncthreads();

        for (int m = 0; m < BB; m += 4) {
            for (int i = j; i < 4 * 128; i += 384) {
                const int r = i >> 7, c = i & 127;
                const int b = m + r;
                const float* src = which
                    ? (g_h0 + ((size_t)t * BB + b) * HH)
                    : (X + ((size_t)b * TT + t) * DD);
                sm->g.x[r][c] = src[c];
            }
            __syncthreads();

            u64 a0 = f2u(bj, 0.f), b0 = 0;
            u64 a1 = f2u(bj, 0.f), b1 = 0;
            u64 a2 = f2u(bj, 0.f), b2 = 0;
            u64 a3 = f2u(bj, 0.f), b3 = 0;
            const ulonglong2* r0 = (const ulonglong2*)sm->g.x[0];
            const ulonglong2* r1 = (const ulonglong2*)sm->g.x[1];
            const ulonglong2* r2 = (const ulonglong2*)sm->g.x[2];
            const ulonglong2* r3 = (const ulonglong2*)sm->g.x[3];
            #pragma unroll
            for (int k = 0; k < 32; k++) {
                ulonglong2 v0 = r0[k], v1 = r1[k], v2 = r2[k], v3 = r3[k];
                fma2(a0, v0.x, w[2*k]); fma2(b0, v0.y, w[2*k+1]);
                fma2(a1, v1.x, w[2*k]); fma2(b1, v1.y, w[2*k+1]);
                fma2(a2, v2.x, w[2*k]); fma2(b2, v2.y, w[2*k+1]);
                fma2(a3, v3.x, w[2*k]); fma2(b3, v3.y, w[2*k+1]);
            }
            dst[((size_t)t * BB + m + 0) * GG + j] = hsum(a0, b0);
            dst[((size_t)t * BB + m + 1) * GG + j] = hsum(a1, b1);
            dst[((size_t)t * BB + m + 2) * GG + j] = hsum(a2, b2);
            dst[((size_t)t * BB + m + 3) * GG + j] = hsum(a3, b3);
            __syncthreads();
        }
        if (j == 0) red_rel(&fout[t]);
    }
}

// ---------------------------------------------------------------------------
// REC role: 1 batch per CTA (proven fastest per-step config).
//   dot (all 384 thr, 64 fma2) -> bar A -> gates (thr 0-127) -> bar B
//   gi loads for step t at loop top (flag fin[t] verified by j383 spin at t-1)
// ---------------------------------------------------------------------------
__device__ void rec_role(SmemAll* smu,
                         const float* __restrict__ Whh,
                         const float* __restrict__ bhh,
                         int layer, int b,
                         float* __restrict__ hout)
{
    SmemRec* sm = &smu->r;
    const int j = threadIdx.x;
    const int e = j & 127;
    const bool isGate = (j < 128);

    u64 w[64];
    {
        const ulonglong2* wr = (const ulonglong2*)(Whh + (size_t)j * 128);
        #pragma unroll
        for (int k = 0; k < 32; k++) { ulonglong2 v = wr[k]; w[2*k] = v.x; w[2*k+1] = v.y; }
    }
    const float bj = bhh[j];

    const float* gi = layer ? g_gi1 : g_gi0;
    const unsigned* fin = layer ? g_f_gi1 : g_f_gi0;
    const size_t S = (size_t)BB * GG;
    const float* gb = gi + (size_t)b * GG;
    float* h0p = g_h0 + (size_t)b * HH + e;

    if (isGate) sm->h[e] = 0.0f;
    if (j == 0) spin_ge(&fin[0], 1);
    __syncthreads();

    float hreg = 0.0f;
    const ulonglong2* h16 = (const ulonglong2*)sm->h;

    for (int t = 0; t < TT; t++) {
        // gi loads for this step (fin[t] guaranteed CTA-wide)
        float gr = 0.f, gz = 0.f, gn = 0.f;
        if (isGate) {
            const float* p = gb + (size_t)t * S;
            gr = p[e]; gz = p[e + 128]; gn = p[e + 256];
        }

        // dot: gh row j = b_hh[j] + h . W_hh[j]
        u64 a0 = f2u(bj, 0.f), a1 = 0;
        #pragma unroll
        for (int k = 0; k < 16; k++) {
            ulonglong2 v = h16[k];
            fma2(a0, v.x, w[2*k]);
            fma2(a1, v.y, w[2*k+1]);
        }
        #pragma unroll
        for (int k = 16; k < 32; k++) {
            ulonglong2 v = h16[k];
            fma2(a0, v.x, w[2*k]);
            fma2(a1, v.y, w[2*k+1]);
        }
        sm->gh[j] = hsum(a0, a1);
        __syncthreads();                       // (A) gh ready

        if (j == 383 && t + 1 < TT) spin_ge(&fin[t + 1], 1);

        if (isGate) {
            const float r = fsig(sm->gh[e] + gr);
            const float z = fsig(sm->gh[e + 128] + gz);
            const float n = ftanh(gn + r * sm->gh[e + 256]);
            hreg = n + z * (hreg - n);
            sm->h[e] = hreg;
            if (layer == 0) h0p[(size_t)t * BB * HH] = hreg;
        }
        __syncthreads();                       // (B) h published; fin[t+1] known
        if (layer == 0 && j == 0) red_rel(&g_f_h0[t]);
    }

    if (isGate) hout[(size_t)b * HH + e] = hreg;
}

// ---------------------------------------------------------------------------
__global__ __launch_bounds__(384, 1) void gru_fused(
    const float* __restrict__ x,
    const float* __restrict__ W_ih0, const float* __restrict__ W_hh0,
    const float* __restrict__ b_ih0, const float* __restrict__ b_hh0,
    const float* __restrict__ W_ih1, const float* __restrict__ W_hh1,
    const float* __restrict__ b_ih1, const float* __restrict__ b_hh1,
    float* __restrict__ out)
{
    __shared__ __align__(16) SmemAll sm;
    const int bid = blockIdx.x;

    // Prologue: ALL CTAs cooperatively compute gi0 (striped over t).
    gemm_role(&sm, x, W_ih0, b_ih0, /*which=*/0, bid, NCTA);

    // Roles.
    if (bid < 64) {
        rec_role(&sm, W_hh0, b_hh0, /*layer=*/0, bid, out);
    } else if (bid < 128) {
        rec_role(&sm, W_hh1, b_hh1, /*layer=*/1, bid - 64, out + BB * HH);
    } else {
        gemm_role(&sm, nullptr, W_ih1, b_ih1, /*which=*/1, bid - 128, N_G1);
    }
}

extern "C" void kernel_launch(void* const* d_in, const int* in_sizes, int n_in,
                              void* d_out, int out_size)
{
    const float* x     = (const float*)d_in[0];
    const float* W_ih0 = (const float*)d_in[1];
    const float* W_hh0 = (const float*)d_in[2];
    const float* b_ih0 = (const float*)d_in[3];
    const float* b_hh0 = (const float*)d_in[4];
    const float* W_ih1 = (const float*)d_in[5];
    const float* W_hh1 = (const float*)d_in[6];
    const float* b_ih1 = (const float*)d_in[7];
    const float* b_hh1 = (const float*)d_in[8];
    float* out = (float*)d_out;   // [L=2, B, H]

    zero_flags<<<(TT + 255) / 256, 256>>>();
    gru_fused<<<NCTA, 384>>>(
        x, W_ih0, W_hh0, b_ih0, b_hh0, W_ih1, W_hh1, b_ih1, b_hh1, out);
}